// round 15
// baseline (speedup 1.0000x reference)
#include <cuda_runtime.h>
#include <cstdint>

#define BATCH 512
#define TLEN  1024
#define NST   64

typedef unsigned long long ull;

// Packed f32x2 helpers (Blackwell FFMA2 path — only reachable via PTX f32x2)
#define FMA2(d, a, b, c) asm("fma.rn.f32x2 %0, %1, %2, %3;" : "=l"(d) : "l"(a), "l"(b), "l"(c))
#define ADD2(d, a, b)    asm("add.rn.f32x2 %0, %1, %2;"     : "=l"(d) : "l"(a), "l"(b))
#define UNPACK2(lo, hi, s) asm("mov.b64 {%0, %1}, %2;"      : "=f"(lo), "=f"(hi) : "l"(s))

// Per-chain named barrier: 4 warps = 128 threads
#define CHAIN_BAR(q) asm volatile("bar.sync %0, 128;" :: "r"(1 + (q)) : "memory")

__device__ __forceinline__ float fexp(float x) {
    float y;
    asm("ex2.approx.f32 %0, %1;" : "=f"(y) : "f"(x * 1.4426950408889634f));
    return y;
}
__device__ __forceinline__ float ex2f(float x) {
    float y;
    asm("ex2.approx.f32 %0, %1;" : "=f"(y) : "f"(x));
    return y;
}
__device__ __forceinline__ float flog(float x) {
    float y;
    asm("lg2.approx.f32 %0, %1;" : "=f"(y) : "f"(x));
    return y * 0.6931471805599453f;
}

// chain index by descending-length rank
__device__ int g_perm[BATCH];

// Bitonic argsort of lengths (ascending), then store descending perm.
__global__ void sort_kernel(const int* __restrict__ lengths) {
    __shared__ unsigned key[BATCH];
    int t = threadIdx.x;
    int len = lengths[t];
    if (len < 1) len = 1;
    key[t] = ((unsigned)len << 16) | (unsigned)t;
    __syncthreads();
    for (int k = 2; k <= BATCH; k <<= 1) {
        for (int j = k >> 1; j > 0; j >>= 1) {
            int ix = t ^ j;
            if (ix > t) {
                unsigned a = key[t], b = key[ix];
                bool up = ((t & k) == 0);
                if (up ? (a > b) : (a < b)) { key[t] = b; key[ix] = a; }
            }
            __syncthreads();
        }
    }
    g_perm[BATCH - 1 - t] = (int)(key[t] & 0xFFFFu);  // descending by length
}

// Half-matvec for one column: 8 broadcast LDS.128 + 16 FFMA2 over my i-half.
// P points at my half's packed pairs (36*h floats into the padded buffer).
__device__ __forceinline__ float half_matvec(const ulonglong2* __restrict__ P,
                                             const ull* __restrict__ cE) {
    ull a0 = 0ull, a1 = 0ull, a2 = 0ull, a3 = 0ull;
    #pragma unroll
    for (int m = 0; m < 8; m += 2) {
        ulonglong2 x = P[m];
        ulonglong2 y = P[m + 1];
        FMA2(a0, x.x, cE[2 * m + 0], a0);
        FMA2(a1, x.y, cE[2 * m + 1], a1);
        FMA2(a2, y.x, cE[2 * m + 2], a2);
        FMA2(a3, y.y, cE[2 * m + 3], a3);
    }
    ADD2(a0, a0, a1);
    ADD2(a2, a2, a3);
    ADD2(a0, a0, a2);
    float slo, shi;
    UNPACK2(slo, shi, a0);
    return slo + shi;
}

// grid=128, block=512: ONE CTA per SM. 4 chains/CTA; chain q = warps {4q..4q+3}
// -> exactly one warp per SMSP when the chain runs solo.
// Thread owns column c = ct>>1, i-half h = ct&1: 16 FFMA2 + 8 LDS.128;
// the two i-half partials combine via intra-warp shfl_xor(1) (adjacent lane).
// w stored with a 16B gap between halves -> conflict-free split reads.
// Anti-paired ranks + per-chain named bar + R14 x4 phase unroll.
__global__ void __launch_bounds__(512, 1) crf_kernel(
    const float* __restrict__ unary,
    const int*   __restrict__ lengths,
    const float* __restrict__ trans,
    float*       __restrict__ out)
{
    const int tid  = threadIdx.x;
    const int q    = tid >> 7;           // chain slot 0..3
    const int ct   = tid & 127;          // thread within chain
    const int c    = ct >> 1;            // my column
    const int h    = ct & 1;             // my i-half
    const int lane = tid & 31;
    const int wch  = ct >> 5;            // warp within chain (0..3)

    // rank -> chain index (anti-paired scheduling; same mapping as R14)
    const int i = blockIdx.x;
    int rank;
    if (q == 0)      rank = 2 * i;                 // longest in CTA
    else if (q == 1) rank = 2 * i + 1;
    else if (q == 2) rank = (BATCH - 1) - 2 * i;   // shortest
    else             rank = (BATCH - 2) - 2 * i;
    const int b = g_perm[rank];

    // E slice for (column c, i-half h): cE[k] = (E[32h+2k][c], E[32h+2k+1][c])
    ull cE[16];
    #pragma unroll
    for (int k = 0; k < 16; k++) {
        float e0 = expf(trans[(32 * h + 2 * k) * NST + c]);
        float e1 = expf(trans[(32 * h + 2 * k + 1) * NST + c]);
        ull pk;
        asm("mov.b64 %0, {%1, %2};" : "=l"(pk) : "f"(e0), "f"(e1));
        cE[k] = pk;
    }

    // padded w buffers: halves at float offsets 0 and 36 (16B gap -> no bank
    // conflicts when h=0/h=1 lanes read different halves in one LDS.128)
    __shared__ __align__(16) float wbuf[4][2][72];   // [chain][buf][padded col]
    __shared__ int   sexp[4];                         // [chain] lag-2 exponent
    __shared__ float ssum[4][4];                      // [chain][warp]

    int len = lengths[b];
    if (len < 1) len = 1;
    const float* ub = unary + (size_t)b * (TLEN * NST);
    const float* pc = ub + c;

    const int cidx = c + ((c >> 5) << 2);   // padded index of my column

    // w0 = exp(u0); h==0 representative publishes
    float w = fexp(pc[0]);
    if (h == 0) wbuf[q][0][cidx] = w;
    if (ct == 0) sexp[q] = 0;

    int ktot = 0;
    // distance-3 register prefetch pipeline of this thread's unary column
    float uA = 0.f, uB = 0.f, uC = 0.f;
    if (len > 1) uA = pc[NST];
    uB = (len > 2) ? pc[2 * NST] : uA;
    uC = (len > 3) ? pc[3 * NST] : uB;
    const float* up = pc + (size_t)((len - 1 < 4) ? (len - 1) : 4) * NST;

    const float L2E = 1.4426950408889634f;

    // hardcoded read pointers (my half) and write pointers (my column)
    const ulonglong2* PB0 = (const ulonglong2*)(wbuf[q][0] + 36 * h);
    const ulonglong2* PB1 = (const ulonglong2*)(wbuf[q][1] + 36 * h);
    float* W0 = &wbuf[q][0][cidx];
    float* W1 = &wbuf[q][1][cidx];

    int t = 1;
    // ---- main loop: 4 steps per iteration, phase-specialized (R14) ----
    for (; t + 3 < len; t += 4) {
        // phase A (t%4==1): read buf0 -> write buf1
        CHAIN_BAR(q);
        {
            float eu = ex2f(uA * L2E);
            float p = half_matvec(PB0, cE);
            float po = __shfl_xor_sync(0xffffffffu, p, 1);
            w = (p + po) * eu;
            if (h == 0) *W1 = w;
            uA = uB; uB = uC; uC = *up;
            up += (t + 4 < len) ? NST : 0;
        }
        // phase B (t%4==2): APPLY renorm; read buf1 -> write buf0
        CHAIN_BAR(q);
        {
            int e = sexp[q];
            ktot += e;
            float eu = ex2f(fmaf(uA, L2E, -(float)e));
            float p = half_matvec(PB1, cE);
            float po = __shfl_xor_sync(0xffffffffu, p, 1);
            w = (p + po) * eu;
            if (h == 0) *W0 = w;
            uA = uB; uB = uC; uC = *up;
            up += (t + 5 < len) ? NST : 0;
        }
        // phase C (t%4==3): read buf0 -> write buf1
        CHAIN_BAR(q);
        {
            float eu = ex2f(uA * L2E);
            float p = half_matvec(PB0, cE);
            float po = __shfl_xor_sync(0xffffffffu, p, 1);
            w = (p + po) * eu;
            if (h == 0) *W1 = w;
            uA = uB; uB = uC; uC = *up;
            up += (t + 6 < len) ? NST : 0;
        }
        // phase D (t%4==0): PUBLISH exponent; read buf1 -> write buf0
        CHAIN_BAR(q);
        {
            float eu = ex2f(uA * L2E);
            float p = half_matvec(PB1, cE);
            float po = __shfl_xor_sync(0xffffffffu, p, 1);
            w = (p + po) * eu;
            if (h == 0) *W0 = w;
            int myE = ((__float_as_int(w) >> 23) & 255) - 127;
            myE = min(max(myE, -100), 100);
            if (ct == 0) sexp[q] = myE;
            uA = uB; uB = uC; uC = *up;
            up += (t + 7 < len) ? NST : 0;
        }
    }

    // ---- epilogue: <=3 steps, general form ----
    int buf = 0;  // main loop always ends writing buf0
    for (; t < len; t++) {
        CHAIN_BAR(q);
        float kf = 0.0f;
        if ((t & 3) == 2) {
            int e = sexp[q];
            ktot += e;
            kf = (float)e;
        }
        float eu = ex2f(fmaf(uA, L2E, -kf));
        float p = half_matvec(buf ? PB1 : PB0, cE);
        float po = __shfl_xor_sync(0xffffffffu, p, 1);
        w = (p + po) * eu;
        if ((t & 3) == 0 && ct == 0) {
            int e2 = ((__float_as_int(w) >> 23) & 255) - 127;
            e2 = min(max(e2, -100), 100);
            sexp[q] = e2;
        }
        if (h == 0) (buf ? W0 : W1)[0] = w;
        uA = uB; uB = uC;
        uC = *up;
        up += (t + 4 < len) ? NST : 0;
        buf ^= 1;
    }

    // out[b] = ktot*ln2 + log(sum_j w_j).
    // Each column's w lives in 2 threads (h=0,1) -> count only h==0 lanes.
    float s = (h == 0) ? w : 0.0f;
    #pragma unroll
    for (int off = 16; off; off >>= 1)
        s += __shfl_xor_sync(0xffffffffu, s, off);
    if (lane == 0) ssum[q][wch] = s;
    CHAIN_BAR(q);
    if (ct == 0)
        out[b] = (float)ktot * 0.6931471805599453f +
                 flog(ssum[q][0] + ssum[q][1] + ssum[q][2] + ssum[q][3]);
}

extern "C" void kernel_launch(void* const* d_in, const int* in_sizes, int n_in,
                              void* d_out, int out_size) {
    const float* unary   = nullptr;
    const int*   lengths = nullptr;
    const float* trans   = nullptr;
    for (int i = 0; i < n_in; i++) {
        if (in_sizes[i] == BATCH * TLEN * NST) unary   = (const float*)d_in[i];
        else if (in_sizes[i] == BATCH)         lengths = (const int*)d_in[i];
        else if (in_sizes[i] == NST * NST)     trans   = (const float*)d_in[i];
    }
    sort_kernel<<<1, BATCH>>>(lengths);
    crf_kernel<<<BATCH / 4, 512>>>(unary, lengths, trans, (float*)d_out);
}

// round 16
// speedup vs baseline: 1.0251x; 1.0251x over previous
#include <cuda_runtime.h>
#include <cstdint>

#define BATCH 512
#define TLEN  1024
#define NST   64

typedef unsigned long long ull;

// Packed f32x2 helpers (Blackwell FFMA2 path — only reachable via PTX f32x2)
#define FMA2(d, a, b, c) asm("fma.rn.f32x2 %0, %1, %2, %3;" : "=l"(d) : "l"(a), "l"(b), "l"(c))
#define ADD2(d, a, b)    asm("add.rn.f32x2 %0, %1, %2;"     : "=l"(d) : "l"(a), "l"(b))
#define UNPACK2(lo, hi, s) asm("mov.b64 {%0, %1}, %2;"      : "=f"(lo), "=f"(hi) : "l"(s))

#define CHAIN_BAR(q) asm volatile("bar.sync %0, 64;" :: "r"(1 + (q)) : "memory")

__device__ __forceinline__ float fexp(float x) {
    float y;
    asm("ex2.approx.f32 %0, %1;" : "=f"(y) : "f"(x * 1.4426950408889634f));
    return y;
}
__device__ __forceinline__ float ex2f(float x) {
    float y;
    asm("ex2.approx.f32 %0, %1;" : "=f"(y) : "f"(x));
    return y;
}
__device__ __forceinline__ float flog(float x) {
    float y;
    asm("lg2.approx.f32 %0, %1;" : "=f"(y) : "f"(x));
    return y * 0.6931471805599453f;
}

// chain index by descending-length rank
__device__ int g_perm[BATCH];

// Bitonic argsort of lengths (ascending), then store descending perm.
__global__ void sort_kernel(const int* __restrict__ lengths) {
    __shared__ unsigned key[BATCH];
    int t = threadIdx.x;
    int len = lengths[t];
    if (len < 1) len = 1;
    key[t] = ((unsigned)len << 16) | (unsigned)t;
    __syncthreads();
    for (int k = 2; k <= BATCH; k <<= 1) {
        for (int j = k >> 1; j > 0; j >>= 1) {
            int ix = t ^ j;
            if (ix > t) {
                unsigned a = key[t], b = key[ix];
                bool up = ((t & k) == 0);
                if (up ? (a > b) : (a < b)) { key[t] = b; key[ix] = a; }
            }
            __syncthreads();
        }
    }
    g_perm[BATCH - 1 - t] = (int)(key[t] & 0xFFFFu);  // descending by length
}

// 16 broadcast LDS.128 + 32 FFMA2, 4 accumulators (reuse distance 4 instr =
// 12 cyc at rt3 >= lat 4 -> no stall; one fewer fold level in the tail).
__device__ __forceinline__ float matvec_col(const ulonglong2* __restrict__ P,
                                            const ull* __restrict__ cE) {
    ull a0 = 0ull, a1 = 0ull, a2 = 0ull, a3 = 0ull;
    #pragma unroll
    for (int m = 0; m < 16; m += 2) {
        ulonglong2 x = P[m];
        ulonglong2 y = P[m + 1];
        FMA2(a0, x.x, cE[2 * m + 0], a0);
        FMA2(a1, x.y, cE[2 * m + 1], a1);
        FMA2(a2, y.x, cE[2 * m + 2], a2);
        FMA2(a3, y.y, cE[2 * m + 3], a3);
    }
    ADD2(a0, a0, a1);
    ADD2(a2, a2, a3);
    ADD2(a0, a0, a2);
    float slo, shi;
    UNPACK2(slo, shi, a0);
    return slo + shi;
}

// grid=128, block=256: ONE CTA per SM. 4 chains/CTA; chain q = warps {2q,2q+1}.
// Anti-paired ranks -> long chain runs solo on its SMSP pair.
// x4 phase-specialized unroll (R14); phases reordered so each warp reaches
// STS(w) -> bar with nothing in between (unary bookkeeping hoisted earlier).
__global__ void __launch_bounds__(256, 1) crf_kernel(
    const float* __restrict__ unary,
    const int*   __restrict__ lengths,
    const float* __restrict__ trans,
    float*       __restrict__ out)
{
    const int tid  = threadIdx.x;
    const int q    = tid >> 6;           // chain slot 0..3
    const int t64  = tid & 63;           // thread within chain
    const int hw   = t64 >> 5;           // warp-half within chain (0/1)
    const int lane = tid & 31;
    const int c    = t64;                // my column

    // rank -> chain index (anti-paired scheduling)
    const int i = blockIdx.x;
    int rank;
    if (q == 0)      rank = 2 * i;                 // longest in CTA
    else if (q == 1) rank = 2 * i + 1;
    else if (q == 2) rank = (BATCH - 1) - 2 * i;   // shortest
    else             rank = (BATCH - 2) - 2 * i;
    const int b = g_perm[rank];

    // E column slice computed inline: 32 packed i-pairs
    ull cE[32];
    #pragma unroll
    for (int k = 0; k < 32; k++) {
        float e0 = expf(trans[(2 * k) * NST + c]);
        float e1 = expf(trans[(2 * k + 1) * NST + c]);
        ull pk;
        asm("mov.b64 %0, {%1, %2};" : "=l"(pk) : "f"(e0), "f"(e1));
        cE[k] = pk;
    }

    __shared__ __align__(16) float wbuf[4][2][NST];  // [chain][buf][col]
    __shared__ int   sexp[4];                         // [chain] lag-2 exponent
    __shared__ float ssum[4][2];                      // [chain][warp-half]

    int len = lengths[b];
    if (len < 1) len = 1;
    const float* ub = unary + (size_t)b * (TLEN * NST);
    const float* pc = ub + c;

    // w0 = exp(u0); sexp init 0 so phase-B applies are no-ops until first publish
    float w = fexp(pc[0]);
    wbuf[q][0][c] = w;
    if (t64 == 0) sexp[q] = 0;

    int ktot = 0;
    // distance-3 register prefetch pipeline of this thread's unary column
    float uA = 0.f, uB = 0.f, uC = 0.f;
    if (len > 1) uA = pc[NST];
    uB = (len > 2) ? pc[2 * NST] : uA;
    uC = (len > 3) ? pc[3 * NST] : uB;
    const float* up = pc + (size_t)((len - 1 < 4) ? (len - 1) : 4) * NST;

    const float L2E = 1.4426950408889634f;

    // hardcoded buffer pointers (no per-step address math)
    const ulonglong2* PB0 = (const ulonglong2*)wbuf[q][0];
    const ulonglong2* PB1 = (const ulonglong2*)wbuf[q][1];
    float* W0 = &wbuf[q][0][c];
    float* W1 = &wbuf[q][1][c];

    int t = 1;
    // ---- main loop: 4 steps per iteration, phase-specialized ----
    for (; t + 3 < len; t += 4) {
        // phase A (t%4==1): read buf0 -> write buf1
        CHAIN_BAR(q);
        {
            float eu = ex2f(uA * L2E);
            uA = uB; uB = uC; uC = *up;            // bookkeeping BEFORE matvec
            up += (t + 4 < len) ? NST : 0;
            w = matvec_col(PB0, cE) * eu;
            *W1 = w;                               // STS -> bar, nothing between
        }
        // phase B (t%4==2): APPLY renorm; read buf1 -> write buf0
        CHAIN_BAR(q);
        {
            int e = sexp[q];
            ktot += e;
            float eu = ex2f(fmaf(uA, L2E, -(float)e));
            uA = uB; uB = uC; uC = *up;
            up += (t + 5 < len) ? NST : 0;
            w = matvec_col(PB1, cE) * eu;
            *W0 = w;
        }
        // phase C (t%4==3): read buf0 -> write buf1
        CHAIN_BAR(q);
        {
            float eu = ex2f(uA * L2E);
            uA = uB; uB = uC; uC = *up;
            up += (t + 6 < len) ? NST : 0;
            w = matvec_col(PB0, cE) * eu;
            *W1 = w;
        }
        // phase D (t%4==0): read buf1 -> write buf0; PUBLISH exponent after STS
        CHAIN_BAR(q);
        {
            float eu = ex2f(uA * L2E);
            uA = uB; uB = uC; uC = *up;
            up += (t + 7 < len) ? NST : 0;
            w = matvec_col(PB1, cE) * eu;
            *W0 = w;
            int myE = ((__float_as_int(w) >> 23) & 255) - 127;
            myE = min(max(myE, -100), 100);
            if (c == 0) sexp[q] = myE;
        }
    }

    // ---- epilogue: <=3 steps, general form (keeps phase behavior) ----
    int buf = 0;  // main loop always ends writing buf0
    for (; t < len; t++) {
        CHAIN_BAR(q);
        float kf = 0.0f;
        if ((t & 3) == 2) {
            int e = sexp[q];
            ktot += e;
            kf = (float)e;
        }
        float eu = ex2f(fmaf(uA, L2E, -kf));
        const ulonglong2* P = buf ? PB1 : PB0;
        w = matvec_col(P, cE) * eu;
        if ((t & 3) == 0 && c == 0) {
            int e2 = ((__float_as_int(w) >> 23) & 255) - 127;
            e2 = min(max(e2, -100), 100);
            sexp[q] = e2;
        }
        (buf ? W0 : W1)[0] = w;
        uA = uB; uB = uC;
        uC = *up;
        up += (t + 4 < len) ? NST : 0;
        buf ^= 1;
    }

    // out[b] = ktot*ln2 + log(sum_j w_j): warp reduce, combine 2 warps via smem
    float s = w;
    #pragma unroll
    for (int off = 16; off; off >>= 1)
        s += __shfl_xor_sync(0xffffffffu, s, off);
    if (lane == 0) ssum[q][hw] = s;
    CHAIN_BAR(q);
    if (c == 0)
        out[b] = (float)ktot * 0.6931471805599453f + flog(ssum[q][0] + ssum[q][1]);
}

extern "C" void kernel_launch(void* const* d_in, const int* in_sizes, int n_in,
                              void* d_out, int out_size) {
    const float* unary   = nullptr;
    const int*   lengths = nullptr;
    const float* trans   = nullptr;
    for (int i = 0; i < n_in; i++) {
        if (in_sizes[i] == BATCH * TLEN * NST) unary   = (const float*)d_in[i];
        else if (in_sizes[i] == BATCH)         lengths = (const int*)d_in[i];
        else if (in_sizes[i] == NST * NST)     trans   = (const float*)d_in[i];
    }
    sort_kernel<<<1, BATCH>>>(lengths);
    crf_kernel<<<BATCH / 4, 256>>>(unary, lengths, trans, (float*)d_out);
}

// round 17
// speedup vs baseline: 1.2039x; 1.1744x over previous
#include <cuda_runtime.h>
#include <cstdint>

#define BATCH 512
#define TLEN  1024
#define NST   64

typedef unsigned long long ull;

// Packed f32x2 helpers (Blackwell FFMA2 path — only reachable via PTX f32x2)
#define FMA2(d, a, b, c) asm("fma.rn.f32x2 %0, %1, %2, %3;" : "=l"(d) : "l"(a), "l"(b), "l"(c))
#define ADD2(d, a, b)    asm("add.rn.f32x2 %0, %1, %2;"     : "=l"(d) : "l"(a), "l"(b))
#define UNPACK2(lo, hi, s) asm("mov.b64 {%0, %1}, %2;"      : "=f"(lo), "=f"(hi) : "l"(s))

#define CHAIN_BAR(q) asm volatile("bar.sync %0, 64;" :: "r"(1 + (q)) : "memory")

__device__ __forceinline__ float fexp(float x) {
    float y;
    asm("ex2.approx.f32 %0, %1;" : "=f"(y) : "f"(x * 1.4426950408889634f));
    return y;
}
__device__ __forceinline__ float ex2f(float x) {
    float y;
    asm("ex2.approx.f32 %0, %1;" : "=f"(y) : "f"(x));
    return y;
}
__device__ __forceinline__ float flog(float x) {
    float y;
    asm("lg2.approx.f32 %0, %1;" : "=f"(y) : "f"(x));
    return y * 0.6931471805599453f;
}

// 16 broadcast LDS.128 + 32 FFMA2, 8 accumulators (R14 matvec, verbatim)
__device__ __forceinline__ float matvec_col(const ulonglong2* __restrict__ P,
                                            const ull* __restrict__ cE) {
    ull a0 = 0ull, a1 = 0ull, a2 = 0ull, a3 = 0ull;
    ull a4 = 0ull, a5 = 0ull, a6 = 0ull, a7 = 0ull;
    #pragma unroll
    for (int m = 0; m < 16; m += 4) {
        ulonglong2 x = P[m];
        ulonglong2 y = P[m + 1];
        ulonglong2 z = P[m + 2];
        ulonglong2 v = P[m + 3];
        FMA2(a0, x.x, cE[2 * m + 0], a0);
        FMA2(a1, x.y, cE[2 * m + 1], a1);
        FMA2(a2, y.x, cE[2 * m + 2], a2);
        FMA2(a3, y.y, cE[2 * m + 3], a3);
        FMA2(a4, z.x, cE[2 * m + 4], a4);
        FMA2(a5, z.y, cE[2 * m + 5], a5);
        FMA2(a6, v.x, cE[2 * m + 6], a6);
        FMA2(a7, v.y, cE[2 * m + 7], a7);
    }
    ADD2(a0, a0, a1);
    ADD2(a2, a2, a3);
    ADD2(a4, a4, a5);
    ADD2(a6, a6, a7);
    ADD2(a0, a0, a2);
    ADD2(a4, a4, a6);
    ADD2(a0, a0, a4);
    float slo, shi;
    UNPACK2(slo, shi, a0);
    return slo + shi;
}

// grid=128, block=256: ONE CTA per SM. 4 chains/CTA; chain q = warps {2q,2q+1}.
// Anti-paired ranks -> long chain runs solo on its SMSP pair.
// Sort folded into the prologue: every CTA redundantly bitonic-sorts the 512
// (len<<16|idx) keys in its own smem (~1-2us parallel), replacing the serial
// grid=1 sort launch (~4-7us). Main loop is R14 byte-for-byte.
__global__ void __launch_bounds__(256, 1) crf_kernel(
    const float* __restrict__ unary,
    const int*   __restrict__ lengths,
    const float* __restrict__ trans,
    float*       __restrict__ out)
{
    const int tid  = threadIdx.x;
    const int q    = tid >> 6;           // chain slot 0..3
    const int t64  = tid & 63;           // thread within chain
    const int hw   = t64 >> 5;           // warp-half within chain (0/1)
    const int lane = tid & 31;
    const int c    = t64;                // my column

    // ---- in-CTA bitonic sort of (len<<16)|idx, ascending ----
    __shared__ unsigned skey[BATCH];
    {
        int l0 = lengths[tid];
        int l1 = lengths[tid + 256];
        if (l0 < 1) l0 = 1;
        if (l1 < 1) l1 = 1;
        skey[tid]       = ((unsigned)l0 << 16) | (unsigned)tid;
        skey[tid + 256] = ((unsigned)l1 << 16) | (unsigned)(tid + 256);
    }
    __syncthreads();
    for (int k = 2; k <= BATCH; k <<= 1) {
        for (int j = k >> 1; j > 0; j >>= 1) {
            #pragma unroll
            for (int ee = 0; ee < 2; ee++) {
                int e  = tid + 256 * ee;
                int ix = e ^ j;
                if (ix > e) {
                    unsigned a = skey[e], bkey = skey[ix];
                    bool up = ((e & k) == 0);
                    if (up ? (a > bkey) : (a < bkey)) { skey[e] = bkey; skey[ix] = a; }
                }
            }
            __syncthreads();
        }
    }

    // rank -> chain index (anti-paired scheduling; descending rank r = skey[511-r])
    const int i = blockIdx.x;
    int rank;
    if (q == 0)      rank = 2 * i;                 // longest in CTA
    else if (q == 1) rank = 2 * i + 1;
    else if (q == 2) rank = (BATCH - 1) - 2 * i;   // shortest
    else             rank = (BATCH - 2) - 2 * i;
    const unsigned mykey = skey[BATCH - 1 - rank];
    const int b   = (int)(mykey & 0xFFFFu);
    const int len = (int)(mykey >> 16);

    // E column slice computed inline: 32 packed i-pairs
    ull cE[32];
    #pragma unroll
    for (int k = 0; k < 32; k++) {
        float e0 = expf(trans[(2 * k) * NST + c]);
        float e1 = expf(trans[(2 * k + 1) * NST + c]);
        ull pk;
        asm("mov.b64 %0, {%1, %2};" : "=l"(pk) : "f"(e0), "f"(e1));
        cE[k] = pk;
    }

    __shared__ __align__(16) float wbuf[4][2][NST];  // [chain][buf][col]
    __shared__ int   sexp[4];                         // [chain] lag-2 exponent
    __shared__ float ssum[4][2];                      // [chain][warp-half]

    const float* ub = unary + (size_t)b * (TLEN * NST);
    const float* pc = ub + c;

    // w0 = exp(u0); sexp init 0 so phase-B applies are no-ops until first publish
    float w = fexp(pc[0]);
    wbuf[q][0][c] = w;
    if (t64 == 0) sexp[q] = 0;

    int ktot = 0;
    // distance-3 register prefetch pipeline of this thread's unary column
    float uA = 0.f, uB = 0.f, uC = 0.f;
    if (len > 1) uA = pc[NST];
    uB = (len > 2) ? pc[2 * NST] : uA;
    uC = (len > 3) ? pc[3 * NST] : uB;
    const float* up = pc + (size_t)((len - 1 < 4) ? (len - 1) : 4) * NST;

    const float L2E = 1.4426950408889634f;

    // hardcoded buffer pointers (no per-step address math)
    const ulonglong2* PB0 = (const ulonglong2*)wbuf[q][0];
    const ulonglong2* PB1 = (const ulonglong2*)wbuf[q][1];
    float* W0 = &wbuf[q][0][c];
    float* W1 = &wbuf[q][1][c];

    // chains must not enter the loop before all CTA threads finish the sort
    // reads of skey and the wbuf publishes above
    __syncthreads();

    int t = 1;
    // ---- main loop: 4 steps per iteration, phase-specialized (R14) ----
    for (; t + 3 < len; t += 4) {
        // phase A (t%4==1): read buf0 -> write buf1
        CHAIN_BAR(q);
        {
            float eu = ex2f(uA * L2E);
            w = matvec_col(PB0, cE) * eu;
            *W1 = w;
            uA = uB; uB = uC; uC = *up;
            up += (t + 4 < len) ? NST : 0;
        }
        // phase B (t%4==2): APPLY renorm; read buf1 -> write buf0
        CHAIN_BAR(q);
        {
            int e = sexp[q];
            ktot += e;
            float eu = ex2f(fmaf(uA, L2E, -(float)e));
            w = matvec_col(PB1, cE) * eu;
            *W0 = w;
            uA = uB; uB = uC; uC = *up;
            up += (t + 5 < len) ? NST : 0;
        }
        // phase C (t%4==3): read buf0 -> write buf1
        CHAIN_BAR(q);
        {
            float eu = ex2f(uA * L2E);
            w = matvec_col(PB0, cE) * eu;
            *W1 = w;
            uA = uB; uB = uC; uC = *up;
            up += (t + 6 < len) ? NST : 0;
        }
        // phase D (t%4==0): PUBLISH exponent; read buf1 -> write buf0
        CHAIN_BAR(q);
        {
            float eu = ex2f(uA * L2E);
            w = matvec_col(PB1, cE) * eu;
            *W0 = w;
            int myE = ((__float_as_int(w) >> 23) & 255) - 127;
            myE = min(max(myE, -100), 100);
            if (c == 0) sexp[q] = myE;
            uA = uB; uB = uC; uC = *up;
            up += (t + 7 < len) ? NST : 0;
        }
    }

    // ---- epilogue: <=3 steps, general form (keeps phase behavior) ----
    int buf = 0;  // main loop always ends writing buf0
    for (; t < len; t++) {
        CHAIN_BAR(q);
        float kf = 0.0f;
        if ((t & 3) == 2) {
            int e = sexp[q];
            ktot += e;
            kf = (float)e;
        }
        float eu = ex2f(fmaf(uA, L2E, -kf));
        const ulonglong2* P = buf ? PB1 : PB0;
        w = matvec_col(P, cE) * eu;
        if ((t & 3) == 0 && c == 0) {
            int e2 = ((__float_as_int(w) >> 23) & 255) - 127;
            e2 = min(max(e2, -100), 100);
            sexp[q] = e2;
        }
        (buf ? W0 : W1)[0] = w;
        uA = uB; uB = uC;
        uC = *up;
        up += (t + 4 < len) ? NST : 0;
        buf ^= 1;
    }

    // out[b] = ktot*ln2 + log(sum_j w_j): warp reduce, combine 2 warps via smem
    float s = w;
    #pragma unroll
    for (int off = 16; off; off >>= 1)
        s += __shfl_xor_sync(0xffffffffu, s, off);
    if (lane == 0) ssum[q][hw] = s;
    CHAIN_BAR(q);
    if (c == 0)
        out[b] = (float)ktot * 0.6931471805599453f + flog(ssum[q][0] + ssum[q][1]);
}

extern "C" void kernel_launch(void* const* d_in, const int* in_sizes, int n_in,
                              void* d_out, int out_size) {
    const float* unary   = nullptr;
    const int*   lengths = nullptr;
    const float* trans   = nullptr;
    for (int i = 0; i < n_in; i++) {
        if (in_sizes[i] == BATCH * TLEN * NST) unary   = (const float*)d_in[i];
        else if (in_sizes[i] == BATCH)         lengths = (const int*)d_in[i];
        else if (in_sizes[i] == NST * NST)     trans   = (const float*)d_in[i];
    }
    crf_kernel<<<BATCH / 4, 256>>>(unary, lengths, trans, (float*)d_out);
}